// round 9
// baseline (speedup 1.0000x reference)
#include <cuda_runtime.h>
#include <cuda_fp16.h>

#define N_USERS 200000
#define N_ITEMS 100000
#define NNODES  300000
#define NE      5000000
#define BATCH   4096
#define NEPAD   (NE + 3 * NNODES + 16)
#define NB      ((NNODES + 1023) / 1024)

// ---------------- scratch (static device globals; no allocation) ----------------
__device__ float4 g_x0[(size_t)NNODES * 16];     // fp32 E0 (concat of embeddings)
__device__ float4 g_x1[(size_t)NNODES * 16];     // fp32 layer-1 output
__device__ float4 g_x2[(size_t)NNODES * 16];     // fp32 layer-2 output (marked rows only)
__device__ int    g_rowstart[NNODES];
__device__ int    g_counts[NNODES];
__device__ int    g_cursor[NNODES];
__device__ char   g_flag[NNODES];                // sampled rows
__device__ char   g_mark[NNODES];                // rows needing layer-2 output
__device__ int    g_mlist[NNODES];
__device__ int    g_nmark;
__device__ unsigned long long g_ss[NB];          // lookback scan status: (sum<<2)|state
__device__ __align__(16) int2 g_edges[NEPAD];    // (col, bits(val)), row-sorted, 4-padded

// ---------------- 1: count (x4 unrolled) + E0 fp32 copy + sample flags ----------------
__global__ void k_countinit(const int* __restrict__ rows,
                            const float* __restrict__ user_emb,
                            const float* __restrict__ item_emb,
                            const int* __restrict__ users,
                            const int* __restrict__ pos,
                            const int* __restrict__ neg) {
    int t = blockIdx.x * blockDim.x + threadIdx.x;
    if (t < NE / 4) {
        int4 r = __ldcs(&((const int4*)rows)[t]);
        atomicAdd(&g_counts[r.x], 1);            // result unused -> REDG (fire & forget)
        atomicAdd(&g_counts[r.y], 1);
        atomicAdd(&g_counts[r.z], 1);
        atomicAdd(&g_counts[r.w], 1);
    }
    if (t < NNODES * 16) {
        int node = t >> 4, k = t & 15;
        const float4* src = (node < N_USERS)
            ? (const float4*)user_emb + (size_t)node * 16
            : (const float4*)item_emb + (size_t)(node - N_USERS) * 16;
        g_x0[t] = src[k];
    }
    if (t < BATCH) {
        int u = users[t], p = N_USERS + pos[t], n = N_USERS + neg[t];
        g_flag[u] = 1; g_flag[p] = 1; g_flag[n] = 1;
        g_mark[u] = 1; g_mark[p] = 1; g_mark[n] = 1;
    }
}

// ---------------- 2: single-pass decoupled-lookback scan of padded counts ----------------
__global__ void __launch_bounds__(1024) k_scanLB() {
    __shared__ int sh[1024];
    __shared__ int s_prefix;
    int tid = threadIdx.x, b = blockIdx.x;
    int i = b * 1024 + tid;
    int c = (i < NNODES) ? g_counts[i] : 0;
    int v = (c + 3) & ~3;                      // pad rows to multiple of 4 edges
    sh[tid] = v;
    __syncthreads();
    #pragma unroll
    for (int off = 1; off < 1024; off <<= 1) {
        int t = (tid >= off) ? sh[tid - off] : 0;
        __syncthreads();
        sh[tid] += t;
        __syncthreads();
    }
    int incl = sh[tid];
    int total = sh[1023];
    if (tid == 0) {
        if (b == 0) {
            atomicExch(&g_ss[0], ((unsigned long long)(unsigned)total << 2) | 2ull);
            s_prefix = 0;
        } else {
            atomicExch(&g_ss[b], ((unsigned long long)(unsigned)total << 2) | 1ull);
            int run = 0;
            for (int p = b - 1; ; p--) {
                unsigned long long s;
                do { s = atomicOr(&g_ss[p], 0ull); } while (!(s & 3ull));
                run += (int)(s >> 2);
                if ((s & 3ull) == 2ull) break;
            }
            atomicExch(&g_ss[b], ((unsigned long long)(unsigned)(run + total) << 2) | 2ull);
            s_prefix = run;
        }
    }
    __syncthreads();
    if (i < NNODES) {
        int excl = s_prefix + incl - v;
        g_rowstart[i] = excl;
        g_cursor[i]   = excl;
    }
}

// ---------------- 3: scatter (x4, MLP=4) + 2-hop marking + padding ----------------
__global__ void k_scatterpad(const int* __restrict__ rows,
                             const int* __restrict__ cols,
                             const float* __restrict__ vals) {
    int t = blockIdx.x * blockDim.x + threadIdx.x;
    if (t < NE / 4) {
        int4   r = __ldcs(&((const int4*)rows)[t]);
        int4   c = __ldcs(&((const int4*)cols)[t]);
        float4 v = __ldcs(&((const float4*)vals)[t]);
        int p0 = atomicAdd(&g_cursor[r.x], 1);   // 4 independent ATOMG chains
        int p1 = atomicAdd(&g_cursor[r.y], 1);
        int p2 = atomicAdd(&g_cursor[r.z], 1);
        int p3 = atomicAdd(&g_cursor[r.w], 1);
        g_edges[p0] = make_int2(c.x, __float_as_int(v.x));
        g_edges[p1] = make_int2(c.y, __float_as_int(v.y));
        g_edges[p2] = make_int2(c.z, __float_as_int(v.z));
        g_edges[p3] = make_int2(c.w, __float_as_int(v.w));
        // 2-hop marking: columns of flagged rows need layer-2 output
        if (g_flag[r.x]) g_mark[c.x] = 1;
        if (g_flag[r.y]) g_mark[c.y] = 1;
        if (g_flag[r.z]) g_mark[c.z] = 1;
        if (g_flag[r.w]) g_mark[c.w] = 1;
    } else if (t - NE / 4 < NNODES) {
        int i = t - NE / 4;
        int c = g_counts[i];
        int pc = (c + 3) & ~3;
        int base = g_rowstart[i];
        for (int j = c; j < pc; j++) g_edges[base + j] = make_int2(0, 0);
    }
}

// ---------------- compaction of marked rows (warp-aggregated atomic) ----------------
__global__ void k_compact() {
    int i = blockIdx.x * blockDim.x + threadIdx.x;
    bool m = (i < NNODES) && g_mark[i];
    unsigned ballot = __ballot_sync(0xffffffffu, m);
    int cnt = __popc(ballot);
    int base = 0;
    if ((threadIdx.x & 31) == 0 && cnt) base = atomicAdd(&g_nmark, cnt);
    base = __shfl_sync(0xffffffffu, base, 0);
    if (m) {
        int off = __popc(ballot & ((1u << (threadIdx.x & 31)) - 1u));
        g_mlist[base + off] = i;
    }
}

// ---------------- SpMM core: warp = 2 groups x 16 lanes; pure fp32, zero cvt ----------
#define PACK2(dst, v) asm("mov.b64 %0, {%1, %1};" : "=l"(dst) : "f"(v))

// acc += {f0,f1} * vv2  (packed f32x2 fma; pack likely folds to a reg pair)
#define FMA2F(acc, f0, f1, vv2)                                                 \
    asm("{\n\t"                                                                 \
        ".reg .b64 d;\n\t"                                                      \
        "mov.b64 d, {%1, %2};\n\t"                                              \
        "fma.rn.f32x2 %0, d, %3, %0;\n\t"                                       \
        "}" : "+l"(acc) : "f"(f0), "f"(f1), "l"(vv2))

// row SpMM over fp32 features. g in {0,1}, k in 0..15. Row stride = 256 B.
// pc is a multiple of 4; loop consumes exactly pc edges, no tail.
#define ROW_SPMM32(Eb, Xb, pc)                                                  \
    unsigned long long sA = 0, sB = 0;                                          \
    unsigned kb = (unsigned)(k << 4);                                           \
    for (int it = 0; it + 4 <= pc; it += 4) {                                   \
        int2 ea = *(const int2*)(Eb + ((unsigned)it << 3));                     \
        int2 eb = *(const int2*)(Eb + ((unsigned)(it + 2) << 3));               \
        float4 xa = *(const float4*)(Xb + (((unsigned)ea.x << 8) + kb));        \
        float4 xb = *(const float4*)(Xb + (((unsigned)eb.x << 8) + kb));        \
        unsigned long long va2, vb2;                                            \
        PACK2(va2, __int_as_float(ea.y));                                       \
        PACK2(vb2, __int_as_float(eb.y));                                       \
        FMA2F(sA, xa.x, xa.y, va2);                                             \
        FMA2F(sB, xa.z, xa.w, va2);                                             \
        FMA2F(sA, xb.x, xb.y, vb2);                                             \
        FMA2F(sB, xb.z, xb.w, vb2);                                             \
    }                                                                           \
    float s0, s1, s2, s3;                                                       \
    asm("mov.b64 {%0, %1}, %2;" : "=f"(s0), "=f"(s1) : "l"(sA));                \
    asm("mov.b64 {%0, %1}, %2;" : "=f"(s2), "=f"(s3) : "l"(sB));                \
    s0 += __shfl_xor_sync(0xffffffffu, s0, 16);                                 \
    s1 += __shfl_xor_sync(0xffffffffu, s1, 16);                                 \
    s2 += __shfl_xor_sync(0xffffffffu, s2, 16);                                 \
    s3 += __shfl_xor_sync(0xffffffffu, s3, 16);

__device__ __forceinline__ void spmm_row32(int gw, int g, int k,
                                           const char* __restrict__ Xb,
                                           float4* __restrict__ Xout) {
    int base = g_rowstart[gw];
    int pc   = (g_counts[gw] + 3) & ~3;
    const char* Eb = (const char*)(g_edges + base + g);

    ROW_SPMM32(Eb, Xb, pc);

    if (g == 0) Xout[(size_t)gw * 16 + k] = make_float4(s0, s1, s2, s3);
}

// layer 1: all rows (8 warps/block)
__global__ void __launch_bounds__(256, 8) k_spmm(const float4* __restrict__ X,
                                                 float4* __restrict__ Xout) {
    int gw = blockIdx.x * 8 + (threadIdx.x >> 5);
    if (gw >= NNODES) return;
    int lane = threadIdx.x & 31;
    spmm_row32(gw, lane >> 4, lane & 15, (const char*)X, Xout);
}

// layer 2: only marked rows (grid-strided over compacted list)
__global__ void __launch_bounds__(256, 8) k_spmm2(const float4* __restrict__ X,
                                                  float4* __restrict__ Xout) {
    int nm = g_nmark;
    int lane = threadIdx.x & 31;
    int g = lane >> 4, k = lane & 15;
    int stride = gridDim.x * 8;
    for (int w = blockIdx.x * 8 + (threadIdx.x >> 5); w < nm; w += stride) {
        spmm_row32(g_mlist[w], g, k, (const char*)X, Xout);
    }
}

// ---------------- fused layer 3 + output assembly (12288 rows) ----------------
__global__ void __launch_bounds__(256) k_final(const int* __restrict__ users,
                                               const int* __restrict__ pos,
                                               const int* __restrict__ neg,
                                               float* __restrict__ out) {
    int w = blockIdx.x * 8 + (threadIdx.x >> 5);
    if (w >= 3 * BATCH) return;
    int lane = threadIdx.x & 31;
    int g = lane >> 4, k = lane & 15;
    int kk = w / BATCH;
    int b = w - kk * BATCH;
    int row = (kk == 0) ? users[b] : (N_USERS + ((kk == 1) ? pos[b] : neg[b]));

    int base = g_rowstart[row];
    int pc   = (g_counts[row] + 3) & ~3;
    const char* Eb = (const char*)(g_edges + base + g);
    const char* Xb = (const char*)g_x2;

    ROW_SPMM32(Eb, Xb, pc);   // layer-3 partial at this row

    if (g == 0) {
        size_t o = (size_t)row * 16 + k;
        float4 e0 = g_x0[o];
        float4 l1 = g_x1[o];
        float4 l2 = g_x2[o];
        float4 r;
        r.x = (e0.x + l1.x + l2.x + s0) * 0.25f;
        r.y = (e0.y + l1.y + l2.y + s1) * 0.25f;
        r.z = (e0.z + l1.z + l2.z + s2) * 0.25f;
        r.w = (e0.w + l1.w + l2.w + s3) * 0.25f;
        ((float4*)out)[(size_t)w * 16 + k] = r;
    }
}

// ---------------- launch ----------------
extern "C" void kernel_launch(void* const* d_in, const int* in_sizes, int n_in,
                              void* d_out, int out_size) {
    const float* user_emb = (const float*)d_in[0];
    const float* item_emb = (const float*)d_in[1];
    const float* adj_vals = (const float*)d_in[2];
    const int*   adj_rows = (const int*)d_in[3];
    const int*   adj_cols = (const int*)d_in[4];
    const int*   users    = (const int*)d_in[5];
    const int*   pos      = (const int*)d_in[6];
    const int*   neg      = (const int*)d_in[7];
    float* out = (float*)d_out;

    void *p_x0, *p_x1, *p_x2, *p_cnt, *p_flag, *p_mark, *p_nmark, *p_ss;
    cudaGetSymbolAddress(&p_x0, g_x0);
    cudaGetSymbolAddress(&p_x1, g_x1);
    cudaGetSymbolAddress(&p_x2, g_x2);
    cudaGetSymbolAddress(&p_cnt, g_counts);
    cudaGetSymbolAddress(&p_flag, g_flag);
    cudaGetSymbolAddress(&p_mark, g_mark);
    cudaGetSymbolAddress(&p_nmark, g_nmark);
    cudaGetSymbolAddress(&p_ss, g_ss);

    const int T = 256;

    // zeroing via memset (graph-capturable, no kernel launch)
    cudaMemsetAsync(p_cnt, 0, NNODES * sizeof(int), 0);
    cudaMemsetAsync(p_flag, 0, NNODES, 0);
    cudaMemsetAsync(p_mark, 0, NNODES, 0);
    cudaMemsetAsync(p_nmark, 0, sizeof(int), 0);
    cudaMemsetAsync(p_ss, 0, NB * sizeof(unsigned long long), 0);

    // 1: count(x4) + fp32 E0 copy + flags  (4.8M threads covers all index spaces)
    int ciThreads = NNODES * 16;
    k_countinit<<<(ciThreads + T - 1) / T, T>>>(adj_rows, user_emb, item_emb, users, pos, neg);
    // 2: single-pass scan
    k_scanLB<<<NB, 1024>>>();
    // 3: scatter(x4) + 2-hop mark + pad
    int scThreads = NE / 4 + NNODES;
    k_scatterpad<<<(scThreads + T - 1) / T, T>>>(adj_rows, adj_cols, adj_vals);

    // 4: layer 1 over all nodes (4th kernel -> profiled)
    int spmmBlocks = (NNODES + 7) / 8;
    k_spmm<<<spmmBlocks, 256>>>((const float4*)p_x0, (float4*)p_x1);

    // 5: compact marked rows
    k_compact<<<(NNODES + T - 1) / T, T>>>();

    // 6: layer 2 over marked rows only
    k_spmm2<<<2048, 256>>>((const float4*)p_x1, (float4*)p_x2);

    // 7: layer 3 at sampled rows + output assembly
    int finBlocks = (3 * BATCH + 7) / 8;
    k_final<<<finBlocks, 256>>>(users, pos, neg, out);
}

// round 10
// speedup vs baseline: 1.3287x; 1.3287x over previous
#include <cuda_runtime.h>
#include <cuda_fp16.h>

#define N_USERS 200000
#define N_ITEMS 100000
#define NNODES  300000
#define NE      5000000
#define BATCH   4096
#define NEPAD   (NE + 3 * NNODES + 16)
#define NB      ((NNODES + 1023) / 1024)

// ---------------- scratch (static device globals; no allocation) ----------------
// Everything needing per-call zeroing lives in one struct -> ONE memset.
struct ZB {
    int  counts[NNODES];
    unsigned long long ss[NB];   // lookback scan status: (sum<<2)|state
    int  nmark;
    char flag[NNODES];           // sampled rows (need fp32 l1/l2)
    char mark[NNODES];           // rows needing layer-2 output
};
__device__ ZB     g_z;
__device__ int4   g_xa[(size_t)NNODES * 8];      // fp16 features ping (8 halves per int4)
__device__ int4   g_xb[(size_t)NNODES * 8];      // fp16 features pong
__device__ float4 g_l1f[(size_t)NNODES * 16];    // fp32 layer-1 rows (flagged only)
__device__ float4 g_l2f[(size_t)NNODES * 16];    // fp32 layer-2 rows (flagged only)
__device__ int2   g_rowmeta[NNODES];             // (rowstart, count)
__device__ int    g_cursor[NNODES];
__device__ int    g_mlist[NNODES];
__device__ __align__(16) int2 g_edges[NEPAD];    // (col, bits(val)), row-sorted, 4-padded

// ---------------- 1: count (x4 unrolled) + E0 fp16 init + sample flags ----------------
__global__ void k_countinit(const int* __restrict__ rows,
                            const float* __restrict__ user_emb,
                            const float* __restrict__ item_emb,
                            const int* __restrict__ users,
                            const int* __restrict__ pos,
                            const int* __restrict__ neg) {
    int t = blockIdx.x * blockDim.x + threadIdx.x;
    if (t < NE / 4) {
        int4 r = __ldcs(&((const int4*)rows)[t]);
        atomicAdd(&g_z.counts[r.x], 1);          // result unused -> REDG (fire & forget)
        atomicAdd(&g_z.counts[r.y], 1);
        atomicAdd(&g_z.counts[r.z], 1);
        atomicAdd(&g_z.counts[r.w], 1);
    }
    if (t < NNODES * 8) {
        int node = t >> 3, k = t & 7;
        const float4* src = (node < N_USERS)
            ? (const float4*)user_emb + (size_t)node * 16
            : (const float4*)item_emb + (size_t)(node - N_USERS) * 16;
        float4 a = __ldcs(&src[2 * k]);
        float4 b = __ldcs(&src[2 * k + 1]);
        __half2 h0 = __floats2half2_rn(a.x, a.y);
        __half2 h1 = __floats2half2_rn(a.z, a.w);
        __half2 h2 = __floats2half2_rn(b.x, b.y);
        __half2 h3 = __floats2half2_rn(b.z, b.w);
        int4 o;
        o.x = *(int*)&h0; o.y = *(int*)&h1; o.z = *(int*)&h2; o.w = *(int*)&h3;
        g_xa[t] = o;
    }
    if (t < BATCH) {
        int u = users[t], p = N_USERS + pos[t], n = N_USERS + neg[t];
        g_z.flag[u] = 1; g_z.flag[p] = 1; g_z.flag[n] = 1;
        g_z.mark[u] = 1; g_z.mark[p] = 1; g_z.mark[n] = 1;
    }
}

// ---------------- 2: single-pass decoupled-lookback scan of padded counts ----------------
__global__ void __launch_bounds__(1024) k_scanLB() {
    __shared__ int sh[1024];
    __shared__ int s_prefix;
    int tid = threadIdx.x, b = blockIdx.x;
    int i = b * 1024 + tid;
    int c = (i < NNODES) ? g_z.counts[i] : 0;
    int v = (c + 3) & ~3;                      // pad rows to multiple of 4 edges
    sh[tid] = v;
    __syncthreads();
    #pragma unroll
    for (int off = 1; off < 1024; off <<= 1) {
        int t = (tid >= off) ? sh[tid - off] : 0;
        __syncthreads();
        sh[tid] += t;
        __syncthreads();
    }
    int incl = sh[tid];
    int total = sh[1023];
    if (tid == 0) {
        if (b == 0) {
            atomicExch(&g_z.ss[0], ((unsigned long long)(unsigned)total << 2) | 2ull);
            s_prefix = 0;
        } else {
            atomicExch(&g_z.ss[b], ((unsigned long long)(unsigned)total << 2) | 1ull);
            int run = 0;
            for (int p = b - 1; ; p--) {
                unsigned long long s;
                do { s = atomicOr(&g_z.ss[p], 0ull); } while (!(s & 3ull));
                run += (int)(s >> 2);
                if ((s & 3ull) == 2ull) break;
            }
            atomicExch(&g_z.ss[b], ((unsigned long long)(unsigned)(run + total) << 2) | 2ull);
            s_prefix = run;
        }
    }
    __syncthreads();
    if (i < NNODES) {
        int excl = s_prefix + incl - v;
        g_rowmeta[i] = make_int2(excl, c);
        g_cursor[i]  = excl;
    }
}

// ---------------- 3: scatter (x4, MLP=4) + 2-hop marking + padding ----------------
__global__ void k_scatterpad(const int* __restrict__ rows,
                             const int* __restrict__ cols,
                             const float* __restrict__ vals) {
    int t = blockIdx.x * blockDim.x + threadIdx.x;
    if (t < NE / 4) {
        int4   r = __ldcs(&((const int4*)rows)[t]);
        int4   c = __ldcs(&((const int4*)cols)[t]);
        float4 v = __ldcs(&((const float4*)vals)[t]);
        int p0 = atomicAdd(&g_cursor[r.x], 1);   // 4 independent ATOMG chains
        int p1 = atomicAdd(&g_cursor[r.y], 1);
        int p2 = atomicAdd(&g_cursor[r.z], 1);
        int p3 = atomicAdd(&g_cursor[r.w], 1);
        g_edges[p0] = make_int2(c.x, __float_as_int(v.x));
        g_edges[p1] = make_int2(c.y, __float_as_int(v.y));
        g_edges[p2] = make_int2(c.z, __float_as_int(v.z));
        g_edges[p3] = make_int2(c.w, __float_as_int(v.w));
        // 2-hop marking: columns of flagged rows need layer-2 output
        if (g_z.flag[r.x]) g_z.mark[c.x] = 1;
        if (g_z.flag[r.y]) g_z.mark[c.y] = 1;
        if (g_z.flag[r.z]) g_z.mark[c.z] = 1;
        if (g_z.flag[r.w]) g_z.mark[c.w] = 1;
    } else if (t - NE / 4 < NNODES) {
        int i = t - NE / 4;
        int2 m = g_rowmeta[i];
        int pc = (m.y + 3) & ~3;
        for (int j = m.y; j < pc; j++) g_edges[m.x + j] = make_int2(0, 0);
    }
}

// ---------------- SpMM core (R6 FFMA2 form): warp = 4 groups x 8 lanes ----------------
#define FMA2(acc, h2bits, vv2)                                                  \
    asm("{\n\t"                                                                 \
        ".reg .b16 h0, h1;\n\t"                                                 \
        ".reg .f32 f0, f1;\n\t"                                                 \
        ".reg .b64 d;\n\t"                                                      \
        "mov.b32 {h0, h1}, %1;\n\t"                                             \
        "cvt.f32.f16 f0, h0;\n\t"                                               \
        "cvt.f32.f16 f1, h1;\n\t"                                               \
        "mov.b64 d, {f0, f1};\n\t"                                              \
        "fma.rn.f32x2 %0, d, %2, %0;\n\t"                                       \
        "}" : "+l"(acc) : "r"(h2bits), "l"(vv2))

#define PACK2(dst, v) asm("mov.b64 %0, {%1, %1};" : "=l"(dst) : "f"(v))

#define ACC8(xi, vv2)                                                           \
    { FMA2(sA, (xi).x, vv2); FMA2(sB, (xi).y, vv2);                             \
      FMA2(sC, (xi).z, vv2); FMA2(sD, (xi).w, vv2); }

#define REDUCE_XGROUP()                                                         \
    {                                                                           \
        _Pragma("unroll")                                                       \
        for (int off = 8; off <= 16; off <<= 1) {                               \
            s0.x += __shfl_xor_sync(0xffffffffu, s0.x, off);                    \
            s0.y += __shfl_xor_sync(0xffffffffu, s0.y, off);                    \
            s1.x += __shfl_xor_sync(0xffffffffu, s1.x, off);                    \
            s1.y += __shfl_xor_sync(0xffffffffu, s1.y, off);                    \
            s2.x += __shfl_xor_sync(0xffffffffu, s2.x, off);                    \
            s2.y += __shfl_xor_sync(0xffffffffu, s2.y, off);                    \
            s3.x += __shfl_xor_sync(0xffffffffu, s3.x, off);                    \
            s3.y += __shfl_xor_sync(0xffffffffu, s3.y, off);                    \
        }                                                                       \
    }

#define ROW_SPMM(Eb, Xb, pc)                                                    \
    unsigned long long sA = 0, sB = 0, sC = 0, sD = 0;                          \
    unsigned kb = (unsigned)(k << 4);                                           \
    int it = 0;                                                                 \
    for (; it + 8 <= pc; it += 8) {                                             \
        int2 ea = *(const int2*)(Eb + ((unsigned)it << 3));                     \
        int2 eb = *(const int2*)(Eb + ((unsigned)(it + 4) << 3));               \
        int4 xa = *(const int4*)(Xb + (((unsigned)ea.x << 7) + kb));            \
        int4 xb = *(const int4*)(Xb + (((unsigned)eb.x << 7) + kb));            \
        unsigned long long va2, vb2;                                            \
        PACK2(va2, __int_as_float(ea.y));                                       \
        PACK2(vb2, __int_as_float(eb.y));                                       \
        ACC8(xa, va2);                                                          \
        ACC8(xb, vb2);                                                          \
    }                                                                           \
    if (it < pc) {                                                              \
        int2 ea = *(const int2*)(Eb + ((unsigned)it << 3));                     \
        int4 xa = *(const int4*)(Xb + (((unsigned)ea.x << 7) + kb));            \
        unsigned long long va2;                                                 \
        PACK2(va2, __int_as_float(ea.y));                                       \
        ACC8(xa, va2);                                                          \
    }                                                                           \
    float2 s0, s1, s2, s3;                                                      \
    asm("mov.b64 {%0, %1}, %2;" : "=f"(s0.x), "=f"(s0.y) : "l"(sA));            \
    asm("mov.b64 {%0, %1}, %2;" : "=f"(s1.x), "=f"(s1.y) : "l"(sB));            \
    asm("mov.b64 {%0, %1}, %2;" : "=f"(s2.x), "=f"(s2.y) : "l"(sC));            \
    asm("mov.b64 {%0, %1}, %2;" : "=f"(s3.x), "=f"(s3.y) : "l"(sD));

__device__ __forceinline__ void spmm_row(int gw, int g, int k,
                                         const char* __restrict__ Xb,
                                         int4* __restrict__ Xout,
                                         float4* __restrict__ f32out) {
    int2 m = g_rowmeta[gw];
    int pc = (m.y + 3) & ~3;
    const char* Eb = (const char*)(g_edges + m.x + g);

    ROW_SPMM(Eb, Xb, pc);
    REDUCE_XGROUP();

    if (g == 0) {
        __half2 h0 = __float22half2_rn(s0);
        __half2 h1 = __float22half2_rn(s1);
        __half2 h2 = __float22half2_rn(s2);
        __half2 h3 = __float22half2_rn(s3);
        int4 o;
        o.x = *(int*)&h0; o.y = *(int*)&h1; o.z = *(int*)&h2; o.w = *(int*)&h3;
        Xout[(size_t)gw * 8 + k] = o;
        if (g_z.flag[gw]) {
            __stcs(&f32out[(size_t)gw * 16 + 2 * k],     make_float4(s0.x, s0.y, s1.x, s1.y));
            __stcs(&f32out[(size_t)gw * 16 + 2 * k + 1], make_float4(s2.x, s2.y, s3.x, s3.y));
        }
    }
}

// layer 1: all rows; first blocks also compact the marked-row list (fused k_compact)
__global__ void __launch_bounds__(256, 8) k_spmm(const int4* __restrict__ X,
                                                 int4* __restrict__ Xout,
                                                 float4* __restrict__ f32out) {
    if (blockIdx.x < (NNODES + 255) / 256) {
        int i = blockIdx.x * 256 + threadIdx.x;
        bool mk = (i < NNODES) && g_z.mark[i];
        unsigned ballot = __ballot_sync(0xffffffffu, mk);
        int cnt = __popc(ballot);
        int base = 0;
        if ((threadIdx.x & 31) == 0 && cnt) base = atomicAdd(&g_z.nmark, cnt);
        base = __shfl_sync(0xffffffffu, base, 0);
        if (mk) {
            int off = __popc(ballot & ((1u << (threadIdx.x & 31)) - 1u));
            g_mlist[base + off] = i;
        }
    }
    int gw = blockIdx.x * 8 + (threadIdx.x >> 5);
    if (gw >= NNODES) return;
    int lane = threadIdx.x & 31;
    spmm_row(gw, lane >> 3, lane & 7, (const char*)X, Xout, f32out);
}

// layer 2: only marked rows (grid-strided over compacted list)
__global__ void __launch_bounds__(256, 8) k_spmm2(const int4* __restrict__ X,
                                                  int4* __restrict__ Xout,
                                                  float4* __restrict__ f32out) {
    int nm = g_z.nmark;
    int lane = threadIdx.x & 31;
    int g = lane >> 3, k = lane & 7;
    int stride = gridDim.x * 8;
    for (int w = blockIdx.x * 8 + (threadIdx.x >> 5); w < nm; w += stride) {
        int gw = g_mlist[w];
        spmm_row(gw, g, k, (const char*)X, Xout, f32out);
    }
}

// ---------------- fused layer 3 + output assembly (12288 rows) ----------------
__global__ void __launch_bounds__(256) k_final(const int* __restrict__ users,
                                               const int* __restrict__ pos,
                                               const int* __restrict__ neg,
                                               const int4* __restrict__ X2,
                                               const float* __restrict__ user_emb,
                                               const float* __restrict__ item_emb,
                                               float* __restrict__ out) {
    int w = blockIdx.x * 8 + (threadIdx.x >> 5);
    if (w >= 3 * BATCH) return;
    int lane = threadIdx.x & 31;
    int g = lane >> 3, k = lane & 7;
    int kk = w / BATCH;
    int b = w - kk * BATCH;
    int row = (kk == 0) ? users[b] : (N_USERS + ((kk == 1) ? pos[b] : neg[b]));

    int2 m = g_rowmeta[row];
    int pc = (m.y + 3) & ~3;
    const char* Eb = (const char*)(g_edges + m.x + g);
    const char* Xb = (const char*)X2;

    ROW_SPMM(Eb, Xb, pc);
    REDUCE_XGROUP();

    if (g == 0) {
        const float4* e0p = (row < N_USERS)
            ? (const float4*)user_emb + (size_t)row * 16
            : (const float4*)item_emb + (size_t)(row - N_USERS) * 16;
        float4 ea = e0p[2 * k],               eb = e0p[2 * k + 1];
        float4 l1a = g_l1f[(size_t)row * 16 + 2 * k], l1b = g_l1f[(size_t)row * 16 + 2 * k + 1];
        float4 l2a = g_l2f[(size_t)row * 16 + 2 * k], l2b = g_l2f[(size_t)row * 16 + 2 * k + 1];
        float4 ra, rb;
        ra.x = (ea.x + l1a.x + l2a.x + s0.x) * 0.25f;
        ra.y = (ea.y + l1a.y + l2a.y + s0.y) * 0.25f;
        ra.z = (ea.z + l1a.z + l2a.z + s1.x) * 0.25f;
        ra.w = (ea.w + l1a.w + l2a.w + s1.y) * 0.25f;
        rb.x = (eb.x + l1b.x + l2b.x + s2.x) * 0.25f;
        rb.y = (eb.y + l1b.y + l2b.y + s2.y) * 0.25f;
        rb.z = (eb.z + l1b.z + l2b.z + s3.x) * 0.25f;
        rb.w = (eb.w + l1b.w + l2b.w + s3.y) * 0.25f;
        ((float4*)out)[(size_t)w * 16 + 2 * k]     = ra;
        ((float4*)out)[(size_t)w * 16 + 2 * k + 1] = rb;
    }
}

// ---------------- launch ----------------
extern "C" void kernel_launch(void* const* d_in, const int* in_sizes, int n_in,
                              void* d_out, int out_size) {
    const float* user_emb = (const float*)d_in[0];
    const float* item_emb = (const float*)d_in[1];
    const float* adj_vals = (const float*)d_in[2];
    const int*   adj_rows = (const int*)d_in[3];
    const int*   adj_cols = (const int*)d_in[4];
    const int*   users    = (const int*)d_in[5];
    const int*   pos      = (const int*)d_in[6];
    const int*   neg      = (const int*)d_in[7];
    float* out = (float*)d_out;

    void *p_z, *p_xa, *p_xb, *p_l1, *p_l2;
    cudaGetSymbolAddress(&p_z, g_z);
    cudaGetSymbolAddress(&p_xa, g_xa);
    cudaGetSymbolAddress(&p_xb, g_xb);
    cudaGetSymbolAddress(&p_l1, g_l1f);
    cudaGetSymbolAddress(&p_l2, g_l2f);

    const int T = 256;

    // single merged zeroing memset (graph-capturable)
    cudaMemsetAsync(p_z, 0, sizeof(ZB), 0);

    // 1: count(x4) + fp16 init + flags  (2.4M threads covers all index spaces)
    int ciThreads = NNODES * 8;
    k_countinit<<<(ciThreads + T - 1) / T, T>>>(adj_rows, user_emb, item_emb, users, pos, neg);
    // 2: single-pass scan -> rowmeta + cursor
    k_scanLB<<<NB, 1024>>>();
    // 3: scatter(x4) + 2-hop mark + pad
    int scThreads = NE / 4 + NNODES;
    k_scatterpad<<<(scThreads + T - 1) / T, T>>>(adj_rows, adj_cols, adj_vals);

    // 4: layer 1 over all nodes + fused compaction (4th kernel -> profiled)
    int spmmBlocks = (NNODES + 7) / 8;
    k_spmm<<<spmmBlocks, 256>>>((const int4*)p_xa, (int4*)p_xb, (float4*)p_l1);

    // 5: layer 2 over marked rows only
    k_spmm2<<<2048, 256>>>((const int4*)p_xb, (int4*)p_xa, (float4*)p_l2);

    // 6: layer 3 at sampled rows + output assembly
    int finBlocks = (3 * BATCH + 7) / 8;
    k_final<<<finBlocks, 256>>>(users, pos, neg, (const int4*)p_xa,
                                user_emb, item_emb, out);
}

// round 11
// speedup vs baseline: 1.4736x; 1.1090x over previous
#include <cuda_runtime.h>
#include <cuda_fp16.h>

#define N_USERS 200000
#define N_ITEMS 100000
#define NNODES  300000
#define NE      5000000
#define BATCH   4096
#define NEPAD   (NE + 3 * NNODES + 16)
#define NB      ((NNODES + 1023) / 1024)
#define ZOFF    ((unsigned)((NEPAD - 4) * 8))   // byte offset of 32B zero-edge slot

// ---------------- scratch (static device globals; no allocation) ----------------
struct ZB {
    int  counts[NNODES];
    unsigned long long ss[NB];   // lookback scan status: (sum<<2)|state
    int  nmark;
    char flag[NNODES];           // sampled rows (need fp32 l1/l2)
    char mark[NNODES];           // rows needing layer-2 output
};
__device__ ZB     g_z;
__device__ int4   g_xa[(size_t)NNODES * 8];      // fp16 features ping (8 halves per int4)
__device__ int4   g_xb[(size_t)NNODES * 8];      // fp16 features pong
__device__ float4 g_l1f[(size_t)NNODES * 16];    // fp32 layer-1 rows (flagged only)
__device__ float4 g_l2f[(size_t)NNODES * 16];    // fp32 layer-2 rows (flagged only)
__device__ int2   g_rowmeta[NNODES];             // (rowstart, count)
__device__ int    g_cursor[NNODES];
__device__ int    g_mlist[NNODES];
__device__ __align__(16) int2 g_edges[NEPAD];    // (col, bits(val)), row-sorted, 4-padded

// ---------------- 1: count (x4 unrolled) + E0 fp16 init + sample flags ----------------
__global__ void k_countinit(const int* __restrict__ rows,
                            const float* __restrict__ user_emb,
                            const float* __restrict__ item_emb,
                            const int* __restrict__ users,
                            const int* __restrict__ pos,
                            const int* __restrict__ neg) {
    int t = blockIdx.x * blockDim.x + threadIdx.x;
    if (t < NE / 4) {
        int4 r = __ldcs(&((const int4*)rows)[t]);
        atomicAdd(&g_z.counts[r.x], 1);
        atomicAdd(&g_z.counts[r.y], 1);
        atomicAdd(&g_z.counts[r.z], 1);
        atomicAdd(&g_z.counts[r.w], 1);
    }
    if (t < NNODES * 8) {
        int node = t >> 3, k = t & 7;
        const float4* src = (node < N_USERS)
            ? (const float4*)user_emb + (size_t)node * 16
            : (const float4*)item_emb + (size_t)(node - N_USERS) * 16;
        float4 a = __ldcs(&src[2 * k]);
        float4 b = __ldcs(&src[2 * k + 1]);
        __half2 h0 = __floats2half2_rn(a.x, a.y);
        __half2 h1 = __floats2half2_rn(a.z, a.w);
        __half2 h2 = __floats2half2_rn(b.x, b.y);
        __half2 h3 = __floats2half2_rn(b.z, b.w);
        int4 o;
        o.x = *(int*)&h0; o.y = *(int*)&h1; o.z = *(int*)&h2; o.w = *(int*)&h3;
        g_xa[t] = o;
    }
    if (t < BATCH) {
        int u = users[t], p = N_USERS + pos[t], n = N_USERS + neg[t];
        g_z.flag[u] = 1; g_z.flag[p] = 1; g_z.flag[n] = 1;
        g_z.mark[u] = 1; g_z.mark[p] = 1; g_z.mark[n] = 1;
    }
}

// ---------------- 2: single-pass decoupled-lookback scan of padded counts ----------------
__global__ void __launch_bounds__(1024) k_scanLB() {
    __shared__ int sh[1024];
    __shared__ int s_prefix;
    int tid = threadIdx.x, b = blockIdx.x;
    int i = b * 1024 + tid;
    int c = (i < NNODES) ? g_z.counts[i] : 0;
    int v = (c + 3) & ~3;                      // pad rows to multiple of 4 edges
    sh[tid] = v;
    __syncthreads();
    #pragma unroll
    for (int off = 1; off < 1024; off <<= 1) {
        int t = (tid >= off) ? sh[tid - off] : 0;
        __syncthreads();
        sh[tid] += t;
        __syncthreads();
    }
    int incl = sh[tid];
    int total = sh[1023];
    if (tid == 0) {
        if (b == 0) {
            atomicExch(&g_z.ss[0], ((unsigned long long)(unsigned)total << 2) | 2ull);
            s_prefix = 0;
        } else {
            atomicExch(&g_z.ss[b], ((unsigned long long)(unsigned)total << 2) | 1ull);
            int run = 0;
            for (int p = b - 1; ; p--) {
                unsigned long long s;
                do { s = atomicOr(&g_z.ss[p], 0ull); } while (!(s & 3ull));
                run += (int)(s >> 2);
                if ((s & 3ull) == 2ull) break;
            }
            atomicExch(&g_z.ss[b], ((unsigned long long)(unsigned)(run + total) << 2) | 2ull);
            s_prefix = run;
        }
    }
    __syncthreads();
    if (i < NNODES) {
        int excl = s_prefix + incl - v;
        g_rowmeta[i] = make_int2(excl, c);
        g_cursor[i]  = excl;
    }
}

// ---------------- 3: scatter (x4, MLP=4) + 2-hop marking + padding ----------------
__global__ void k_scatterpad(const int* __restrict__ rows,
                             const int* __restrict__ cols,
                             const float* __restrict__ vals) {
    int t = blockIdx.x * blockDim.x + threadIdx.x;
    if (t < NE / 4) {
        int4   r = __ldcs(&((const int4*)rows)[t]);
        int4   c = __ldcs(&((const int4*)cols)[t]);
        float4 v = __ldcs(&((const float4*)vals)[t]);
        int p0 = atomicAdd(&g_cursor[r.x], 1);
        int p1 = atomicAdd(&g_cursor[r.y], 1);
        int p2 = atomicAdd(&g_cursor[r.z], 1);
        int p3 = atomicAdd(&g_cursor[r.w], 1);
        g_edges[p0] = make_int2(c.x, __float_as_int(v.x));
        g_edges[p1] = make_int2(c.y, __float_as_int(v.y));
        g_edges[p2] = make_int2(c.z, __float_as_int(v.z));
        g_edges[p3] = make_int2(c.w, __float_as_int(v.w));
        if (g_z.flag[r.x]) g_z.mark[c.x] = 1;
        if (g_z.flag[r.y]) g_z.mark[c.y] = 1;
        if (g_z.flag[r.z]) g_z.mark[c.z] = 1;
        if (g_z.flag[r.w]) g_z.mark[c.w] = 1;
    } else if (t - NE / 4 < NNODES) {
        int i = t - NE / 4;
        int2 m = g_rowmeta[i];
        int pc = (m.y + 3) & ~3;
        for (int j = m.y; j < pc; j++) g_edges[m.x + j] = make_int2(0, 0);
        if (i == 0) {   // 32B zero-edge slot for clamped loads
            g_edges[NEPAD - 4] = make_int2(0, 0);
            g_edges[NEPAD - 3] = make_int2(0, 0);
            g_edges[NEPAD - 2] = make_int2(0, 0);
            g_edges[NEPAD - 1] = make_int2(0, 0);
        }
    }
}

// ---------------- SpMM core: warp = 4 groups x 8 lanes, GROUP-PER-ROW ----------------
#define FMA2(acc, h2bits, vv2)                                                  \
    asm("{\n\t"                                                                 \
        ".reg .b16 h0, h1;\n\t"                                                 \
        ".reg .f32 f0, f1;\n\t"                                                 \
        ".reg .b64 d;\n\t"                                                      \
        "mov.b32 {h0, h1}, %1;\n\t"                                             \
        "cvt.f32.f16 f0, h0;\n\t"                                               \
        "cvt.f32.f16 f1, h1;\n\t"                                               \
        "mov.b64 d, {f0, f1};\n\t"                                              \
        "fma.rn.f32x2 %0, d, %2, %0;\n\t"                                       \
        "}" : "+l"(acc) : "r"(h2bits), "l"(vv2))

#define PACK2(dst, v) asm("mov.b64 %0, {%1, %1};" : "=l"(dst) : "f"(v))

#define ACC8(xi, vv2)                                                           \
    { FMA2(sA, (xi).x, vv2); FMA2(sB, (xi).y, vv2);                             \
      FMA2(sC, (xi).z, vv2); FMA2(sD, (xi).w, vv2); }

// Group-per-row loop: 4 edges/group/iter via 2 LDG.128 edge loads; finished
// groups clamp to the zero-edge slot (zero-valued FMAs). No cross-group reduce.
#define ROW_SPMM4(Xb, rowoff, pc, maxpc, k)                                     \
    unsigned long long sA = 0, sB = 0, sC = 0, sD = 0;                          \
    unsigned kb = (unsigned)(k << 4);                                           \
    const char* EB = (const char*)g_edges;                                      \
    for (int it = 0; it < maxpc; it += 4) {                                     \
        unsigned eo = ((unsigned)it < (unsigned)pc)                             \
                          ? rowoff + ((unsigned)it << 3) : ZOFF;                \
        int4 E01 = *(const int4*)(EB + eo);                                     \
        int4 E23 = *(const int4*)(EB + eo + 16);                                \
        int4 x0 = *(const int4*)(Xb + (((unsigned)E01.x << 7) + kb));           \
        int4 x1 = *(const int4*)(Xb + (((unsigned)E01.z << 7) + kb));           \
        unsigned long long v0, v1;                                              \
        PACK2(v0, __int_as_float(E01.y));                                       \
        PACK2(v1, __int_as_float(E01.w));                                       \
        ACC8(x0, v0);                                                           \
        ACC8(x1, v1);                                                           \
        int4 x2 = *(const int4*)(Xb + (((unsigned)E23.x << 7) + kb));           \
        int4 x3 = *(const int4*)(Xb + (((unsigned)E23.z << 7) + kb));           \
        unsigned long long v2, v3;                                              \
        PACK2(v2, __int_as_float(E23.y));                                       \
        PACK2(v3, __int_as_float(E23.w));                                       \
        ACC8(x2, v2);                                                           \
        ACC8(x3, v3);                                                           \
    }                                                                           \
    float2 s0, s1, s2, s3;                                                      \
    asm("mov.b64 {%0, %1}, %2;" : "=f"(s0.x), "=f"(s0.y) : "l"(sA));            \
    asm("mov.b64 {%0, %1}, %2;" : "=f"(s1.x), "=f"(s1.y) : "l"(sB));            \
    asm("mov.b64 {%0, %1}, %2;" : "=f"(s2.x), "=f"(s2.y) : "l"(sC));            \
    asm("mov.b64 {%0, %1}, %2;" : "=f"(s3.x), "=f"(s3.y) : "l"(sD));

// each GROUP processes row `row` fully (valid=false -> zero work, no store)
__device__ __forceinline__ void spmm_row4(int row, bool valid, int k,
                                          const char* __restrict__ Xb,
                                          int4* __restrict__ Xout,
                                          float4* __restrict__ f32out) {
    int2 m = valid ? g_rowmeta[row] : make_int2(0, 0);
    int pc = valid ? ((m.y + 3) & ~3) : 0;
    unsigned rowoff = (unsigned)m.x << 3;
    int maxpc = __reduce_max_sync(0xffffffffu, pc);

    ROW_SPMM4(Xb, rowoff, pc, maxpc, k);

    if (valid) {
        __half2 h0 = __float22half2_rn(s0);
        __half2 h1 = __float22half2_rn(s1);
        __half2 h2 = __float22half2_rn(s2);
        __half2 h3 = __float22half2_rn(s3);
        int4 o;
        o.x = *(int*)&h0; o.y = *(int*)&h1; o.z = *(int*)&h2; o.w = *(int*)&h3;
        Xout[(size_t)row * 8 + k] = o;
        if (g_z.flag[row]) {
            __stcs(&f32out[(size_t)row * 16 + 2 * k],     make_float4(s0.x, s0.y, s1.x, s1.y));
            __stcs(&f32out[(size_t)row * 16 + 2 * k + 1], make_float4(s2.x, s2.y, s3.x, s3.y));
        }
    }
}

// layer 1: all rows, 4 rows per warp; first blocks also compact the marked list
__global__ void __launch_bounds__(256, 7) k_spmm(const int4* __restrict__ X,
                                                 int4* __restrict__ Xout,
                                                 float4* __restrict__ f32out) {
    if (blockIdx.x < (NNODES + 255) / 256) {
        int i = blockIdx.x * 256 + threadIdx.x;
        bool mk = (i < NNODES) && g_z.mark[i];
        unsigned ballot = __ballot_sync(0xffffffffu, mk);
        int cnt = __popc(ballot);
        int base = 0;
        if ((threadIdx.x & 31) == 0 && cnt) base = atomicAdd(&g_z.nmark, cnt);
        base = __shfl_sync(0xffffffffu, base, 0);
        if (mk) {
            int off = __popc(ballot & ((1u << (threadIdx.x & 31)) - 1u));
            g_mlist[base + off] = i;
        }
    }
    int w = blockIdx.x * 8 + (threadIdx.x >> 5);      // warp id; grid exact
    int lane = threadIdx.x & 31;
    int g = lane >> 3, k = lane & 7;
    int row = w * 4 + g;                               // NNODES divisible by 4
    spmm_row4(row, true, k, (const char*)X, Xout, f32out);
}

// layer 2: only marked rows (grid-strided, 4 list entries per warp)
__global__ void __launch_bounds__(256, 7) k_spmm2(const int4* __restrict__ X,
                                                  int4* __restrict__ Xout,
                                                  float4* __restrict__ f32out) {
    int nm = g_z.nmark;
    int wlimit = (nm + 3) >> 2;
    int lane = threadIdx.x & 31;
    int g = lane >> 3, k = lane & 7;
    int stride = gridDim.x * 8;
    for (int w = blockIdx.x * 8 + (threadIdx.x >> 5); w < wlimit; w += stride) {
        int idx = w * 4 + g;
        bool valid = idx < nm;
        int row = valid ? g_mlist[idx] : 0;
        spmm_row4(row, valid, k, (const char*)X, Xout, f32out);
    }
}

// ---------------- fused layer 3 + output assembly (12288 slots, 4 per warp) ----------
__global__ void __launch_bounds__(256, 7) k_final(const int* __restrict__ users,
                                                  const int* __restrict__ pos,
                                                  const int* __restrict__ neg,
                                                  const int4* __restrict__ X2,
                                                  const float* __restrict__ user_emb,
                                                  const float* __restrict__ item_emb,
                                                  float* __restrict__ out) {
    int w = blockIdx.x * 8 + (threadIdx.x >> 5);      // grid exact: 384 blocks
    int lane = threadIdx.x & 31;
    int g = lane >> 3, k = lane & 7;
    int slot = w * 4 + g;                              // 12288 divisible by 4
    int kk = slot / BATCH;
    int b = slot & (BATCH - 1);
    int row = (kk == 0) ? users[b] : (N_USERS + ((kk == 1) ? pos[b] : neg[b]));

    int2 m = g_rowmeta[row];
    int pc = (m.y + 3) & ~3;
    unsigned rowoff = (unsigned)m.x << 3;
    int maxpc = __reduce_max_sync(0xffffffffu, pc);
    const char* Xb = (const char*)X2;

    ROW_SPMM4(Xb, rowoff, pc, maxpc, k);

    const float4* e0p = (row < N_USERS)
        ? (const float4*)user_emb + (size_t)row * 16
        : (const float4*)item_emb + (size_t)(row - N_USERS) * 16;
    float4 ea = e0p[2 * k],               eb = e0p[2 * k + 1];
    float4 l1a = g_l1f[(size_t)row * 16 + 2 * k], l1b = g_l1f[(size_t)row * 16 + 2 * k + 1];
    float4 l2a = g_l2f[(size_t)row * 16 + 2 * k], l2b = g_l2f[(size_t)row * 16 + 2 * k + 1];
    float4 ra, rb;
    ra.x = (ea.x + l1a.x + l2a.x + s0.x) * 0.25f;
    ra.y = (ea.y + l1a.y + l2a.y + s0.y) * 0.25f;
    ra.z = (ea.z + l1a.z + l2a.z + s1.x) * 0.25f;
    ra.w = (ea.w + l1a.w + l2a.w + s1.y) * 0.25f;
    rb.x = (eb.x + l1b.x + l2b.x + s2.x) * 0.25f;
    rb.y = (eb.y + l1b.y + l2b.y + s2.y) * 0.25f;
    rb.z = (eb.z + l1b.z + l2b.z + s3.x) * 0.25f;
    rb.w = (eb.w + l1b.w + l2b.w + s3.y) * 0.25f;
    ((float4*)out)[(size_t)slot * 16 + 2 * k]     = ra;
    ((float4*)out)[(size_t)slot * 16 + 2 * k + 1] = rb;
}

// ---------------- launch ----------------
extern "C" void kernel_launch(void* const* d_in, const int* in_sizes, int n_in,
                              void* d_out, int out_size) {
    const float* user_emb = (const float*)d_in[0];
    const float* item_emb = (const float*)d_in[1];
    const float* adj_vals = (const float*)d_in[2];
    const int*   adj_rows = (const int*)d_in[3];
    const int*   adj_cols = (const int*)d_in[4];
    const int*   users    = (const int*)d_in[5];
    const int*   pos      = (const int*)d_in[6];
    const int*   neg      = (const int*)d_in[7];
    float* out = (float*)d_out;

    void *p_z, *p_xa, *p_xb, *p_l1, *p_l2;
    cudaGetSymbolAddress(&p_z, g_z);
    cudaGetSymbolAddress(&p_xa, g_xa);
    cudaGetSymbolAddress(&p_xb, g_xb);
    cudaGetSymbolAddress(&p_l1, g_l1f);
    cudaGetSymbolAddress(&p_l2, g_l2f);

    const int T = 256;

    // single merged zeroing memset (graph-capturable)
    cudaMemsetAsync(p_z, 0, sizeof(ZB), 0);

    // 1: count(x4) + fp16 init + flags
    int ciThreads = NNODES * 8;
    k_countinit<<<(ciThreads + T - 1) / T, T>>>(adj_rows, user_emb, item_emb, users, pos, neg);
    // 2: single-pass scan -> rowmeta + cursor
    k_scanLB<<<NB, 1024>>>();
    // 3: scatter(x4) + 2-hop mark + pad (+ zero-edge slot)
    int scThreads = NE / 4 + NNODES;
    k_scatterpad<<<(scThreads + T - 1) / T, T>>>(adj_rows, adj_cols, adj_vals);

    // 4: layer 1 over all nodes, 4 rows/warp + fused compaction (profiled)
    k_spmm<<<NNODES / 32, 256>>>((const int4*)p_xa, (int4*)p_xb, (float4*)p_l1);

    // 5: layer 2 over marked rows only
    k_spmm2<<<2048, 256>>>((const int4*)p_xb, (int4*)p_xa, (float4*)p_l2);

    // 6: layer 3 at sampled rows + output assembly
    k_final<<<3 * BATCH / 32, 256>>>(users, pos, neg, (const int4*)p_xa,
                                     user_emb, item_emb, out);
}